// round 14
// baseline (speedup 1.0000x reference)
#include <cuda_runtime.h>

#define H      64
#define NSEG   1024
#define TPB    256
#define PCOLS  192
#define FULLM  0xffffffffu

// ---------------- scratch (no allocations allowed; zero-init at load) -------
__device__ float g_out[NSEG * PCOLS];
__device__ float g_seg_sum[NSEG];

// ---------------- kernel 1: MLP + exp + seg-sum + warp-local pooling --------
// 6 blocks/SM -> 888 resident blocks >= 782-block grid: single wave.
__global__ __launch_bounds__(TPB, 6) void mega_kernel(
    const float* __restrict__ ht, const float* __restrict__ info,
    const float* __restrict__ fut, const int* __restrict__ seg,
    const float* __restrict__ w1, const float* __restrict__ b1,
    const float* __restrict__ w2, const float* __restrict__ b2, int M)
{
    __shared__ __align__(16) float w1s[128 * 16];
    __shared__ __align__(16) float b1s[16];
    __shared__ __align__(16) float w2s[16];
    __shared__ float b2sv;

    const int tid = threadIdx.x;
    const int li  = tid & 31;
    const int wid = tid >> 5;

    for (int i = tid; i < 128 * 16; i += TPB) w1s[i] = w1[i];
    if (tid < 16) { b1s[tid] = b1[tid]; w2s[tid] = w2[tid]; }
    if (tid == 0) b2sv = b2[0];
    __syncthreads();

    const int lane0 = blockIdx.x * TPB + tid;
    const int lane  = (lane0 < M) ? lane0 : (M - 1);   // clamp: OOB dup last row

    // ---- phase 1: per-thread MLP (packed f32x2 accumulators) ----
    unsigned long long hp[8];
#pragma unroll
    for (int q = 0; q < 8; q++)
        hp[q] = reinterpret_cast<const unsigned long long*>(b1s)[q];

#pragma unroll
    for (int half = 0; half < 2; half++) {
        const float4* x4 = reinterpret_cast<const float4*>(half ? info : ht)
                         + (size_t)lane * (H / 4);
#pragma unroll
        for (int kk = 0; kk < H / 4; kk++) {
            float4 xv = x4[kk];
            const int kbase = half * H + kk * 4;
#pragma unroll
            for (int c = 0; c < 4; c++) {
                float x = (&xv.x)[c];
                unsigned long long xx;
                asm("mov.b64 %0, {%1, %1};" : "=l"(xx) : "f"(x));
                const unsigned long long* wr =
                    reinterpret_cast<const unsigned long long*>(&w1s[(kbase + c) * 16]);
#pragma unroll
                for (int q = 0; q < 8; q++)
                    asm("fma.rn.f32x2 %0, %1, %2, %0;"
                        : "+l"(hp[q]) : "l"(xx), "l"(wr[q]));
            }
        }
    }
    float sc = b2sv;
#pragma unroll
    for (int q = 0; q < 8; q++) {
        float lo, hi;
        asm("mov.b64 {%0, %1}, %2;" : "=f"(lo), "=f"(hi) : "l"(hp[q]));
        sc = fmaf(fmaxf(lo, 0.0f), w2s[2 * q + 0], sc);
        sc = fmaf(fmaxf(hi, 0.0f), w2s[2 * q + 1], sc);
    }

    const int s = seg[lane];
    const float ex = (lane0 < M) ? __expf(sc) : 0.0f;   // scores tiny: no max-shift

    // ---- per-segment sum of ex (sorted ids -> warp-segmented reduce) ----
    {
        float v = ex;
#pragma unroll
        for (int o = 1; o < 32; o <<= 1) {
            float u  = __shfl_down_sync(FULLM, v, o);
            int   s2 = __shfl_down_sync(FULLM, s, o);
            if (li + o < 32 && s2 == s) v += u;
        }
        int sp = __shfl_up_sync(FULLM, s, 1);
        if ((li == 0 || sp != s) && v != 0.0f)
            atomicAdd(&g_seg_sum[s], v);
    }

    // ---- phase 2: warp-local pooling of this warp's 32 lanes ----
    const int wbase = blockIdx.x * TPB + wid * 32;
    const float2* hta = reinterpret_cast<const float2*>(ht)   + li;
    const float2* ina = reinterpret_cast<const float2*>(info) + li;
    const float2* fta = reinterpret_cast<const float2*>(fut)  + li;

    const int sp1 = __shfl_up_sync(FULLM, s, 1);
    unsigned bmask = __ballot_sync(FULLM, li > 0 && sp1 != s);
    const bool full_warp = (wbase + 32 <= M);

    float a0 = 0.f, a1 = 0.f, a2 = 0.f, a3 = 0.f, a4 = 0.f, a5 = 0.f;

    if (bmask == 0 && full_warp) {
        // fast path: one segment covers the whole warp (2-row batches)
#pragma unroll
        for (int r = 0; r < 32; r += 2) {
            size_t g0 = (size_t)(wbase + r) * (H / 2);
            float2 h0 = hta[g0], h1 = hta[g0 + 32];
            float2 i0 = ina[g0], i1 = ina[g0 + 32];
            float2 f0 = __ldcs(&fta[g0]), f1 = __ldcs(&fta[g0 + 32]);
            float p0 = __shfl_sync(FULLM, ex, r + 0);
            float p1 = __shfl_sync(FULLM, ex, r + 1);
            a0 = fmaf(p0, h0.x, a0); a1 = fmaf(p0, h0.y, a1);
            a2 = fmaf(p0, i0.x, a2); a3 = fmaf(p0, i0.y, a3);
            a4 = fmaf(p0, f0.x, a4); a5 = fmaf(p0, f0.y, a5);
            a0 = fmaf(p1, h1.x, a0); a1 = fmaf(p1, h1.y, a1);
            a2 = fmaf(p1, i1.x, a2); a3 = fmaf(p1, i1.y, a3);
            a4 = fmaf(p1, f1.x, a4); a5 = fmaf(p1, f1.y, a5);
        }
        const int s0 = __shfl_sync(FULLM, s, 0);
        float* ob = &g_out[s0 * PCOLS + 2 * li];
        atomicAdd(ob,       a0); atomicAdd(ob + 1,   a1);
        atomicAdd(ob + 64,  a2); atomicAdd(ob + 65,  a3);
        atomicAdd(ob + 128, a4); atomicAdd(ob + 129, a5);
    } else {
        // slow path: segment boundary inside warp and/or partial tail warp
        int cur = __shfl_sync(FULLM, s, 0);
        for (int r = 0; r < 32; r++) {
            int gr = wbase + r;
            if (gr >= M) break;                       // uniform across warp
            int   sr = __shfl_sync(FULLM, s,  r);
            float p  = __shfl_sync(FULLM, ex, r);
            if (sr != cur) {
                float* ob = &g_out[cur * PCOLS + 2 * li];
                atomicAdd(ob,       a0); atomicAdd(ob + 1,   a1);
                atomicAdd(ob + 64,  a2); atomicAdd(ob + 65,  a3);
                atomicAdd(ob + 128, a4); atomicAdd(ob + 129, a5);
                a0 = a1 = a2 = a3 = a4 = a5 = 0.f;
                cur = sr;
            }
            size_t g0 = (size_t)gr * (H / 2);
            float2 h = hta[g0], iv = ina[g0], f = __ldcs(&fta[g0]);
            a0 = fmaf(p, h.x,  a0); a1 = fmaf(p, h.y,  a1);
            a2 = fmaf(p, iv.x, a2); a3 = fmaf(p, iv.y, a3);
            a4 = fmaf(p, f.x,  a4); a5 = fmaf(p, f.y,  a5);
        }
        float* ob = &g_out[cur * PCOLS + 2 * li];
        atomicAdd(ob,       a0); atomicAdd(ob + 1,   a1);
        atomicAdd(ob + 64,  a2); atomicAdd(ob + 65,  a3);
        atomicAdd(ob + 128, a4); atomicAdd(ob + 129, a5);
    }
}

// ---------------- kernel 2: finalize (normalize + rezero scratch) -----------
// block b owns segment b: writes out[b,:], zeroes g_out[b,:] and g_seg_sum[b].
__global__ __launch_bounds__(PCOLS) void finalize_kernel(float* __restrict__ out) {
    const int b = blockIdx.x;
    const int j = threadIdx.x;
    const float s = g_seg_sum[b];
    const int idx = b * PCOLS + j;
    out[idx] = g_out[idx] / s;
    g_out[idx] = 0.0f;
    __syncthreads();
    if (j == 0) g_seg_sum[b] = 0.0f;
}

// ---------------- launch ----------------
extern "C" void kernel_launch(void* const* d_in, const int* in_sizes, int n_in,
                              void* d_out, int out_size)
{
    const float* ht   = (const float*)d_in[0];
    const float* info = (const float*)d_in[1];
    const float* fut  = (const float*)d_in[2];
    const int*   seg  = (const int*)  d_in[3];
    const float* w1   = (const float*)d_in[4];
    const float* b1   = (const float*)d_in[5];
    const float* w2   = (const float*)d_in[6];
    const float* b2   = (const float*)d_in[7];
    float* out = (float*)d_out;

    const int M = in_sizes[0] / H;

    mega_kernel<<<(M + TPB - 1) / TPB, TPB>>>(ht, info, fut, seg,
                                              w1, b1, w2, b2, M);

    finalize_kernel<<<NSEG, PCOLS>>>(out);
}